// round 4
// baseline (speedup 1.0000x reference)
#include <cuda_runtime.h>
#include <math.h>
#include <stdint.h>

#define NN 100000
#define NE 1600000
#define F 128
#define KSEL 128
#define CAND_CAP 2048

// ---------------- scratch (device globals; no allocations allowed) ----------
static __device__ unsigned int g_keys[NN];
static __device__ int          g_deg[NN];
static __device__ float        g_dinv[NN];
static __device__ float        g_xw[(size_t)NN * F];
static __device__ float        g_agg[(size_t)NN * F];
static __device__ float        g_xt[KSEL * F];
static __device__ float        g_Wnew[F * F];
static __device__ float        g_inv_norm;
static __device__ unsigned int g_thresh;
static __device__ int          g_ncand;
static __device__ unsigned long long g_cand[CAND_CAP];
static __device__ int          g_top_idx[KSEL];
static __device__ float        g_top_gate[KSEL];

// ---------------- prep: ||p||^-1 and counter reset ---------------------------
__global__ void k_prep(const float* __restrict__ p) {
    __shared__ float red[128];
    int t = threadIdx.x;
    float v = p[t];
    red[t] = v * v;
    __syncthreads();
    for (int s = 64; s > 0; s >>= 1) {
        if (t < s) red[t] += red[t + s];
        __syncthreads();
    }
    if (t == 0) {
        g_inv_norm = 1.0f / sqrtf(red[0]);
        g_ncand = 0;
    }
}

// ---------------- scores: warp-per-node dot(x[i], p) -------------------------
__global__ void k_scores(const float* __restrict__ x, const float* __restrict__ p) {
    int gw = (blockIdx.x * blockDim.x + threadIdx.x) >> 5;
    int lane = threadIdx.x & 31;
    if (gw >= NN) return;
    float4 xv = ((const float4*)(x + (size_t)gw * F))[lane];
    float4 pv = ((const float4*)p)[lane];
    float s = xv.x * pv.x + xv.y * pv.y + xv.z * pv.z + xv.w * pv.w;
    #pragma unroll
    for (int off = 16; off > 0; off >>= 1)
        s += __shfl_xor_sync(0xFFFFFFFFu, s, off);
    if (lane == 0) {
        float sc = s * g_inv_norm;
        unsigned int b = __float_as_uint(sc);
        unsigned int u = (b & 0x80000000u) ? ~b : (b | 0x80000000u);
        g_keys[gw] = u;
        g_deg[gw] = 0;   // zero degree array for later atomic counting
    }
}

// ---------------- exact 128th-largest key via 4x8-bit radix select -----------
__global__ void k_radix() {
    __shared__ unsigned int hist[256];
    __shared__ unsigned int s_prefix;
    __shared__ unsigned int s_krem;
    if (threadIdx.x == 0) { s_prefix = 0u; s_krem = KSEL; }
    for (int shift = 24; shift >= 0; shift -= 8) {
        if (threadIdx.x < 256) hist[threadIdx.x] = 0u;
        __syncthreads();
        unsigned int prefix = s_prefix;
        unsigned int maskhi = (shift == 24) ? 0u : (0xFFFFFFFFu << (shift + 8));
        for (int i = threadIdx.x; i < NN; i += blockDim.x) {
            unsigned int k = g_keys[i];
            if ((k & maskhi) == prefix)
                atomicAdd(&hist[(k >> shift) & 0xFFu], 1u);
        }
        __syncthreads();
        if (threadIdx.x == 0) {
            unsigned int cum = 0, krem = s_krem;
            int b = 255;
            for (; b >= 0; b--) {
                if (cum + hist[b] >= krem) break;
                cum += hist[b];
            }
            if (b < 0) b = 0;
            s_krem = krem - cum;
            s_prefix = prefix | ((unsigned int)b << shift);
        }
        __syncthreads();
    }
    if (threadIdx.x == 0) g_thresh = s_prefix;
}

// ---------------- collect candidates with key >= threshold -------------------
__global__ void k_collect() {
    int i = blockIdx.x * blockDim.x + threadIdx.x;
    if (i >= NN) return;
    unsigned int u = g_keys[i];
    if (u >= g_thresh) {
        int pos = atomicAdd(&g_ncand, 1);
        if (pos < CAND_CAP)
            g_cand[pos] = ((unsigned long long)u << 32)
                        | (unsigned long long)(0xFFFFFFFFu - (unsigned int)i);
    }
}

// ---------------- sort candidates desc (key, then idx asc), emit top-128 -----
__global__ void k_sort() {
    __shared__ unsigned long long s[CAND_CAP];
    int tid = threadIdx.x;
    int n = g_ncand; if (n > CAND_CAP) n = CAND_CAP;
    for (int i = tid; i < CAND_CAP; i += blockDim.x)
        s[i] = (i < n) ? g_cand[i] : 0ull;
    __syncthreads();
    for (int k = 2; k <= CAND_CAP; k <<= 1) {
        for (int j = k >> 1; j > 0; j >>= 1) {
            for (int i = tid; i < CAND_CAP; i += blockDim.x) {
                int ixj = i ^ j;
                if (ixj > i) {
                    bool desc = ((i & k) == 0);
                    unsigned long long a = s[i], b = s[ixj];
                    bool swap = desc ? (a < b) : (a > b);
                    if (swap) { s[i] = b; s[ixj] = a; }
                }
            }
            __syncthreads();
        }
    }
    if (tid < KSEL) {
        unsigned long long v = s[tid];
        unsigned int u = (unsigned int)(v >> 32);
        int idx = (int)(0xFFFFFFFFu - (unsigned int)(v & 0xFFFFFFFFu));
        unsigned int b = (u & 0x80000000u) ? (u & 0x7FFFFFFFu) : ~u;
        float sc = __uint_as_float(b);
        g_top_idx[tid] = idx;
        g_top_gate[tid] = tanhf(sc);
    }
}

// ---------------- x_tilde[j] = x[top_idx[j]] * tanh(top_val[j]) --------------
__global__ void k_xtilde(const float* __restrict__ x) {
    int j = blockIdx.x, c = threadIdx.x;
    int idx = g_top_idx[j];
    float gate = g_top_gate[j];
    g_xt[j * F + c] = x[(size_t)idx * F + c] * gate;
}

// ---------------- GRU step: W_new ------------------------------------------
__global__ void k_gru(const float* __restrict__ W,
                      const float* __restrict__ w_ih, const float* __restrict__ w_hh,
                      const float* __restrict__ b_ih, const float* __restrict__ b_hh) {
    int r = blockIdx.x, c = threadIdx.x;
    __shared__ float xt[F];
    __shared__ float wr[F];
    xt[c] = g_xt[r * F + c];
    wr[c] = W[r * F + c];
    __syncthreads();
    const float* wi0 = w_ih + (size_t)c * F;
    const float* wi1 = w_ih + (size_t)(F + c) * F;
    const float* wi2 = w_ih + (size_t)(2 * F + c) * F;
    const float* wh0 = w_hh + (size_t)c * F;
    const float* wh1 = w_hh + (size_t)(F + c) * F;
    const float* wh2 = w_hh + (size_t)(2 * F + c) * F;
    float gi0 = 0.f, gi1 = 0.f, gi2 = 0.f, gh0 = 0.f, gh1 = 0.f, gh2 = 0.f;
    #pragma unroll 8
    for (int k = 0; k < F; k++) {
        float xk = xt[k], wk = wr[k];
        gi0 += xk * __ldg(wi0 + k);
        gi1 += xk * __ldg(wi1 + k);
        gi2 += xk * __ldg(wi2 + k);
        gh0 += wk * __ldg(wh0 + k);
        gh1 += wk * __ldg(wh1 + k);
        gh2 += wk * __ldg(wh2 + k);
    }
    gi0 += b_ih[c];         gh0 += b_hh[c];
    gi1 += b_ih[F + c];     gh1 += b_hh[F + c];
    gi2 += b_ih[2 * F + c]; gh2 += b_hh[2 * F + c];
    float rg = 1.f / (1.f + expf(-(gi0 + gh0)));
    float z  = 1.f / (1.f + expf(-(gi1 + gh1)));
    float nn = tanhf(gi2 + rg * gh2);
    g_Wnew[r * F + c] = (1.f - z) * nn + z * wr[c];
}

// ---------------- degree count + dinv ---------------------------------------
__global__ void k_degcnt(const int* __restrict__ ei) {
    int e = blockIdx.x * blockDim.x + threadIdx.x;
    if (e >= NE) return;
    atomicAdd(&g_deg[ei[NE + e]], 1);
}

__global__ void k_dinv() {
    int i = blockIdx.x * blockDim.x + threadIdx.x;
    if (i >= NN) return;
    g_dinv[i] = rsqrtf((float)g_deg[i] + 1.0f);
}

// ---------------- xw = x @ W_new  (fp32, smem-staged, 4x4 reg blocking) ------
__global__ void __launch_bounds__(256, 2) k_xw(const float* __restrict__ x) {
    extern __shared__ float smem[];
    float4* Ws = reinterpret_cast<float4*>(smem);     // [128][32] float4 = 64 KB
    float*  xs = smem + F * F;                        // [32][128] floats = 16 KB
    int tx = threadIdx.x & 31;
    int ty = threadIdx.x >> 5;
    // load W_new once
    for (int i = threadIdx.x; i < F * 32; i += 256)
        Ws[i] = ((const float4*)g_Wnew)[i];
    int ntiles = (NN + 31) / 32;
    for (int t = blockIdx.x; t < ntiles; t += gridDim.x) {
        int row0 = t * 32;
        __syncthreads();
        for (int i = threadIdx.x; i < 32 * 32; i += 256) {
            int r = i >> 5, q = i & 31;
            int gr = row0 + r;
            float4 v = (gr < NN) ? ((const float4*)x)[(size_t)gr * 32 + q]
                                 : make_float4(0.f, 0.f, 0.f, 0.f);
            ((float4*)xs)[i] = v;
        }
        __syncthreads();
        const float* xr0 = xs + (ty * 4 + 0) * F;
        const float* xr1 = xs + (ty * 4 + 1) * F;
        const float* xr2 = xs + (ty * 4 + 2) * F;
        const float* xr3 = xs + (ty * 4 + 3) * F;
        float4 a0 = make_float4(0.f, 0.f, 0.f, 0.f), a1 = a0, a2 = a0, a3 = a0;
        #pragma unroll 4
        for (int k = 0; k < F; k += 4) {
            float xv0[4], xv1[4], xv2[4], xv3[4];
            *(float4*)xv0 = *(const float4*)(xr0 + k);
            *(float4*)xv1 = *(const float4*)(xr1 + k);
            *(float4*)xv2 = *(const float4*)(xr2 + k);
            *(float4*)xv3 = *(const float4*)(xr3 + k);
            #pragma unroll
            for (int j = 0; j < 4; j++) {
                float4 w = Ws[(k + j) * 32 + tx];
                a0.x += xv0[j] * w.x; a0.y += xv0[j] * w.y; a0.z += xv0[j] * w.z; a0.w += xv0[j] * w.w;
                a1.x += xv1[j] * w.x; a1.y += xv1[j] * w.y; a1.z += xv1[j] * w.z; a1.w += xv1[j] * w.w;
                a2.x += xv2[j] * w.x; a2.y += xv2[j] * w.y; a2.z += xv2[j] * w.z; a2.w += xv2[j] * w.w;
                a3.x += xv3[j] * w.x; a3.y += xv3[j] * w.y; a3.z += xv3[j] * w.z; a3.w += xv3[j] * w.w;
            }
        }
        int gr0 = row0 + ty * 4;
        if (gr0 + 0 < NN) ((float4*)g_xw)[(size_t)(gr0 + 0) * 32 + tx] = a0;
        if (gr0 + 1 < NN) ((float4*)g_xw)[(size_t)(gr0 + 1) * 32 + tx] = a1;
        if (gr0 + 2 < NN) ((float4*)g_xw)[(size_t)(gr0 + 2) * 32 + tx] = a2;
        if (gr0 + 3 < NN) ((float4*)g_xw)[(size_t)(gr0 + 3) * 32 + tx] = a3;
    }
}

// ---------------- agg init: self-loop term + bias ----------------------------
__global__ void k_initagg(const float* __restrict__ conv_bias) {
    int t = blockIdx.x * blockDim.x + threadIdx.x;
    if (t >= NN * 32) return;
    int i = t >> 5, q = t & 31;
    float d = g_dinv[i];
    float s = d * d;
    float4 xwv = ((const float4*)g_xw)[(size_t)i * 32 + q];
    float4 b = ((const float4*)conv_bias)[q];
    float4 r;
    r.x = xwv.x * s + b.x; r.y = xwv.y * s + b.y;
    r.z = xwv.z * s + b.z; r.w = xwv.w * s + b.w;
    ((float4*)g_agg)[(size_t)i * 32 + q] = r;
}

// ---------------- edge aggregation: warp/edge, vectorized red ----------------
__global__ void k_edge(const int* __restrict__ ei) {
    int gw = (blockIdx.x * blockDim.x + threadIdx.x) >> 5;
    int lane = threadIdx.x & 31;
    if (gw >= NE) return;
    int row = __ldg(ei + gw);
    int col = __ldg(ei + NE + gw);
    float coef = __ldg(g_dinv + row) * __ldg(g_dinv + col);
    float4 v = ((const float4*)(g_xw + (size_t)row * F))[lane];
    v.x *= coef; v.y *= coef; v.z *= coef; v.w *= coef;
    float* dst = g_agg + (size_t)col * F + lane * 4;
    asm volatile("red.global.add.v4.f32 [%0], {%1, %2, %3, %4};"
                 :: "l"(dst), "f"(v.x), "f"(v.y), "f"(v.z), "f"(v.w)
                 : "memory");
}

// ---------------- head: out = relu(agg) @ lin_w^T + lin_b --------------------
__global__ void k_head(const float* __restrict__ lin_w, const float* __restrict__ lin_b,
                       float* __restrict__ out) {
    int gw = (blockIdx.x * blockDim.x + threadIdx.x) >> 5;
    int lane = threadIdx.x & 31;
    if (gw >= NN) return;
    float4 a = ((const float4*)(g_agg + (size_t)gw * F))[lane];
    float4 lw = ((const float4*)lin_w)[lane];
    float s = fmaxf(a.x, 0.f) * lw.x + fmaxf(a.y, 0.f) * lw.y
            + fmaxf(a.z, 0.f) * lw.z + fmaxf(a.w, 0.f) * lw.w;
    #pragma unroll
    for (int off = 16; off > 0; off >>= 1)
        s += __shfl_xor_sync(0xFFFFFFFFu, s, off);
    if (lane == 0) out[gw] = s + lin_b[0];
}

// ---------------- launcher ---------------------------------------------------
extern "C" void kernel_launch(void* const* d_in, const int* in_sizes, int n_in,
                              void* d_out, int out_size) {
    const float* x         = (const float*)d_in[0];
    const int*   ei        = (const int*)d_in[1];
    const float* W         = (const float*)d_in[2];
    const float* p         = (const float*)d_in[3];
    const float* w_ih      = (const float*)d_in[4];
    const float* w_hh      = (const float*)d_in[5];
    const float* b_ih      = (const float*)d_in[6];
    const float* b_hh      = (const float*)d_in[7];
    const float* conv_bias = (const float*)d_in[8];
    const float* lin_w     = (const float*)d_in[9];
    const float* lin_b     = (const float*)d_in[10];
    float* out = (float*)d_out;

    // No static guard (harness forbids call-count-dependent behavior).
    // cudaFuncSetAttribute is not a stream op; calling it every time is
    // idempotent and legal during graph capture.
    cudaFuncSetAttribute(k_xw, cudaFuncAttributeMaxDynamicSharedMemorySize, 81920);

    k_prep<<<1, 128>>>(p);
    k_scores<<<(NN * 32 + 255) / 256, 256>>>(x, p);
    k_radix<<<1, 1024>>>();
    k_collect<<<(NN + 255) / 256, 256>>>();
    k_sort<<<1, 1024>>>();
    k_xtilde<<<KSEL, F>>>(x);
    k_gru<<<F, F>>>(W, w_ih, w_hh, b_ih, b_hh);
    k_degcnt<<<(NE + 255) / 256, 256>>>(ei);
    k_dinv<<<(NN + 255) / 256, 256>>>();
    k_xw<<<304, 256, 81920>>>(x);
    k_initagg<<<(NN * 32 + 255) / 256, 256>>>(conv_bias);
    k_edge<<<(NE * 32 + 255) / 256, 256>>>(ei);
    k_head<<<(NN * 32 + 255) / 256, 256>>>(lin_w, lin_b, out);
}

// round 5
// speedup vs baseline: 1.3519x; 1.3519x over previous
#include <cuda_runtime.h>
#include <math.h>
#include <stdint.h>

#define NN 100000
#define NE 1600000
#define F 128
#define KSEL 128
#define CAND_CAP 2048
#define SCAN_BLK 25          // ceil(100000 / 4096)

typedef unsigned long long u64;

// ---------------- scratch (device globals; no allocations allowed) ----------
static __device__ unsigned int g_keys[NN];
static __device__ int          g_deg[NN];
static __device__ float        g_dinv[NN];
static __device__ int          g_rowstart[NN + 1];
static __device__ int          g_cursor[NN];
static __device__ int          g_srcrow[NE];
static __device__ int          g_bsum[32];
static __device__ int          g_boff[32];
static __device__ float        g_xw[(size_t)NN * F];
static __device__ float        g_xt[KSEL * F];
static __device__ float        g_Wnew[F * F];
static __device__ float        g_inv_norm;
static __device__ unsigned int g_thresh;
static __device__ int          g_ncand;
static __device__ unsigned long long g_cand[CAND_CAP];
static __device__ int          g_top_idx[KSEL];
static __device__ float        g_top_gate[KSEL];

// ---------------- f32x2 packed helpers --------------------------------------
__device__ __forceinline__ u64 pack2(float lo, float hi) {
    u64 r; asm("mov.b64 %0, {%1, %2};" : "=l"(r) : "f"(lo), "f"(hi)); return r;
}
__device__ __forceinline__ void unpack2(u64 v, float& lo, float& hi) {
    asm("mov.b64 {%0, %1}, %2;" : "=f"(lo), "=f"(hi) : "l"(v));
}
__device__ __forceinline__ u64 fma2(u64 a, u64 b, u64 c) {
    u64 d; asm("fma.rn.f32x2 %0, %1, %2, %3;" : "=l"(d) : "l"(a), "l"(b), "l"(c)); return d;
}

// ---------------- prep: ||p||^-1 and counter reset ---------------------------
__global__ void k_prep(const float* __restrict__ p) {
    __shared__ float red[128];
    int t = threadIdx.x;
    float v = p[t];
    red[t] = v * v;
    __syncthreads();
    for (int s = 64; s > 0; s >>= 1) {
        if (t < s) red[t] += red[t + s];
        __syncthreads();
    }
    if (t == 0) {
        g_inv_norm = 1.0f / sqrtf(red[0]);
        g_ncand = 0;
    }
}

// ---------------- scores: warp-per-node dot(x[i], p); zero deg ---------------
__global__ void k_scores(const float* __restrict__ x, const float* __restrict__ p) {
    int gw = (blockIdx.x * blockDim.x + threadIdx.x) >> 5;
    int lane = threadIdx.x & 31;
    if (gw >= NN) return;
    float4 xv = ((const float4*)(x + (size_t)gw * F))[lane];
    float4 pv = ((const float4*)p)[lane];
    float s = xv.x * pv.x + xv.y * pv.y + xv.z * pv.z + xv.w * pv.w;
    #pragma unroll
    for (int off = 16; off > 0; off >>= 1)
        s += __shfl_xor_sync(0xFFFFFFFFu, s, off);
    if (lane == 0) {
        float sc = s * g_inv_norm;
        unsigned int b = __float_as_uint(sc);
        unsigned int u = (b & 0x80000000u) ? ~b : (b | 0x80000000u);
        g_keys[gw] = u;
        g_deg[gw] = 0;
    }
}

// ---------------- exact 128th-largest key via 4x8-bit radix select -----------
__global__ void k_radix() {
    __shared__ unsigned int hist[256];
    __shared__ unsigned int s_prefix;
    __shared__ unsigned int s_krem;
    if (threadIdx.x == 0) { s_prefix = 0u; s_krem = KSEL; }
    for (int shift = 24; shift >= 0; shift -= 8) {
        if (threadIdx.x < 256) hist[threadIdx.x] = 0u;
        __syncthreads();
        unsigned int prefix = s_prefix;
        unsigned int maskhi = (shift == 24) ? 0u : (0xFFFFFFFFu << (shift + 8));
        for (int i = threadIdx.x; i < NN; i += blockDim.x) {
            unsigned int k = g_keys[i];
            if ((k & maskhi) == prefix)
                atomicAdd(&hist[(k >> shift) & 0xFFu], 1u);
        }
        __syncthreads();
        if (threadIdx.x == 0) {
            unsigned int cum = 0, krem = s_krem;
            int b = 255;
            for (; b >= 0; b--) {
                if (cum + hist[b] >= krem) break;
                cum += hist[b];
            }
            if (b < 0) b = 0;
            s_krem = krem - cum;
            s_prefix = prefix | ((unsigned int)b << shift);
        }
        __syncthreads();
    }
    if (threadIdx.x == 0) g_thresh = s_prefix;
}

// ---------------- collect candidates with key >= threshold -------------------
__global__ void k_collect() {
    int i = blockIdx.x * blockDim.x + threadIdx.x;
    if (i >= NN) return;
    unsigned int u = g_keys[i];
    if (u >= g_thresh) {
        int pos = atomicAdd(&g_ncand, 1);
        if (pos < CAND_CAP)
            g_cand[pos] = ((unsigned long long)u << 32)
                        | (unsigned long long)(0xFFFFFFFFu - (unsigned int)i);
    }
}

// ---------------- sort candidates desc (key, then idx asc), emit top-128 -----
__global__ void k_sort() {
    __shared__ unsigned long long s[CAND_CAP];
    int tid = threadIdx.x;
    int n = g_ncand; if (n > CAND_CAP) n = CAND_CAP;
    for (int i = tid; i < CAND_CAP; i += blockDim.x)
        s[i] = (i < n) ? g_cand[i] : 0ull;
    __syncthreads();
    for (int k = 2; k <= CAND_CAP; k <<= 1) {
        for (int j = k >> 1; j > 0; j >>= 1) {
            for (int i = tid; i < CAND_CAP; i += blockDim.x) {
                int ixj = i ^ j;
                if (ixj > i) {
                    bool desc = ((i & k) == 0);
                    unsigned long long a = s[i], b = s[ixj];
                    bool swap = desc ? (a < b) : (a > b);
                    if (swap) { s[i] = b; s[ixj] = a; }
                }
            }
            __syncthreads();
        }
    }
    if (tid < KSEL) {
        unsigned long long v = s[tid];
        unsigned int u = (unsigned int)(v >> 32);
        int idx = (int)(0xFFFFFFFFu - (unsigned int)(v & 0xFFFFFFFFu));
        unsigned int b = (u & 0x80000000u) ? (u & 0x7FFFFFFFu) : ~u;
        float sc = __uint_as_float(b);
        g_top_idx[tid] = idx;
        g_top_gate[tid] = tanhf(sc);
    }
}

// ---------------- x_tilde[j] = x[top_idx[j]] * tanh(top_val[j]) --------------
__global__ void k_xtilde(const float* __restrict__ x) {
    int j = blockIdx.x, c = threadIdx.x;
    int idx = g_top_idx[j];
    float gate = g_top_gate[j];
    g_xt[j * F + c] = x[(size_t)idx * F + c] * gate;
}

// ---------------- GRU step: W_new -------------------------------------------
__global__ void k_gru(const float* __restrict__ W,
                      const float* __restrict__ w_ih, const float* __restrict__ w_hh,
                      const float* __restrict__ b_ih, const float* __restrict__ b_hh) {
    int r = blockIdx.x, c = threadIdx.x;
    __shared__ float xt[F];
    __shared__ float wr[F];
    xt[c] = g_xt[r * F + c];
    wr[c] = W[r * F + c];
    __syncthreads();
    const float* wi0 = w_ih + (size_t)c * F;
    const float* wi1 = w_ih + (size_t)(F + c) * F;
    const float* wi2 = w_ih + (size_t)(2 * F + c) * F;
    const float* wh0 = w_hh + (size_t)c * F;
    const float* wh1 = w_hh + (size_t)(F + c) * F;
    const float* wh2 = w_hh + (size_t)(2 * F + c) * F;
    float gi0 = 0.f, gi1 = 0.f, gi2 = 0.f, gh0 = 0.f, gh1 = 0.f, gh2 = 0.f;
    #pragma unroll 8
    for (int k = 0; k < F; k++) {
        float xk = xt[k], wk = wr[k];
        gi0 += xk * __ldg(wi0 + k);
        gi1 += xk * __ldg(wi1 + k);
        gi2 += xk * __ldg(wi2 + k);
        gh0 += wk * __ldg(wh0 + k);
        gh1 += wk * __ldg(wh1 + k);
        gh2 += wk * __ldg(wh2 + k);
    }
    gi0 += b_ih[c];         gh0 += b_hh[c];
    gi1 += b_ih[F + c];     gh1 += b_hh[F + c];
    gi2 += b_ih[2 * F + c]; gh2 += b_hh[2 * F + c];
    float rg = 1.f / (1.f + expf(-(gi0 + gh0)));
    float z  = 1.f / (1.f + expf(-(gi1 + gh1)));
    float nn = tanhf(gi2 + rg * gh2);
    g_Wnew[r * F + c] = (1.f - z) * nn + z * wr[c];
}

// ---------------- degree count ----------------------------------------------
__global__ void k_degcnt(const int* __restrict__ ei) {
    int e = blockIdx.x * blockDim.x + threadIdx.x;
    if (e >= NE) return;
    atomicAdd(&g_deg[ei[NE + e]], 1);
}

// ---------------- 3-kernel exclusive prefix scan of degrees ------------------
__global__ void k_scan1() {
    __shared__ int ssum[1024];
    int bid = blockIdx.x, t = threadIdx.x;
    int base = bid * 4096 + t * 4;
    int v[4]; int s = 0;
    #pragma unroll
    for (int j = 0; j < 4; j++) {
        int idx = base + j;
        v[j] = (idx < NN) ? g_deg[idx] : 0;
        s += v[j];
    }
    ssum[t] = s;
    __syncthreads();
    for (int off = 1; off < 1024; off <<= 1) {
        int xv = (t >= off) ? ssum[t - off] : 0;
        __syncthreads();
        ssum[t] += xv;
        __syncthreads();
    }
    int run = ssum[t] - s;   // exclusive within block
    if (t == 1023) g_bsum[bid] = ssum[1023];
    #pragma unroll
    for (int j = 0; j < 4; j++) {
        int idx = base + j;
        if (idx < NN) g_rowstart[idx] = run;
        run += v[j];
    }
}

__global__ void k_scan2() {
    int t = threadIdx.x;
    int v = (t < SCAN_BLK) ? g_bsum[t] : 0;
    int orig = v;
    #pragma unroll
    for (int off = 1; off < 32; off <<= 1) {
        int u = __shfl_up_sync(0xFFFFFFFFu, v, off);
        if (t >= off) v += u;
    }
    g_boff[t] = v - orig;    // exclusive
}

__global__ void k_scan3() {
    int i = blockIdx.x * blockDim.x + threadIdx.x;
    if (i >= NN) return;
    int r = g_rowstart[i] + g_boff[i >> 12];
    g_rowstart[i] = r;
    g_cursor[i] = r;
    g_dinv[i] = rsqrtf((float)g_deg[i] + 1.0f);
    if (i == 0) g_rowstart[NN] = NE;
}

// ---------------- fill CSR: srcrow bucketed by col ---------------------------
__global__ void k_fill(const int* __restrict__ ei) {
    int e = blockIdx.x * blockDim.x + threadIdx.x;
    if (e >= NE) return;
    int row = __ldg(ei + e);
    int col = __ldg(ei + NE + e);
    int pos = atomicAdd(&g_cursor[col], 1);
    g_srcrow[pos] = row;
}

// ---------------- xw = x @ W_new  (fp32, smem-staged, packed f32x2) ----------
__global__ void __launch_bounds__(256, 2) k_xw(const float* __restrict__ x) {
    extern __shared__ float smem[];
    float4* Ws = reinterpret_cast<float4*>(smem);     // [128 k][32 colgrp] float4 = 64 KB
    float*  xs = smem + F * F;                        // [32 rows][128] floats = 16 KB
    int tx = threadIdx.x & 31;
    int ty = threadIdx.x >> 5;
    for (int i = threadIdx.x; i < F * 32; i += 256)
        Ws[i] = ((const float4*)g_Wnew)[i];
    int ntiles = (NN + 31) / 32;
    for (int t = blockIdx.x; t < ntiles; t += gridDim.x) {
        int row0 = t * 32;
        __syncthreads();
        for (int i = threadIdx.x; i < 32 * 32; i += 256) {
            int r = i >> 5, q = i & 31;
            int gr = row0 + r;
            float4 v = (gr < NN) ? ((const float4*)x)[(size_t)gr * 32 + q]
                                 : make_float4(0.f, 0.f, 0.f, 0.f);
            ((float4*)xs)[i] = v;
        }
        __syncthreads();
        const float* xr0 = xs + (ty * 4 + 0) * F;
        const float* xr1 = xs + (ty * 4 + 1) * F;
        const float* xr2 = xs + (ty * 4 + 2) * F;
        const float* xr3 = xs + (ty * 4 + 3) * F;
        u64 a0l = 0, a0h = 0, a1l = 0, a1h = 0, a2l = 0, a2h = 0, a3l = 0, a3h = 0;
        {
            float z = 0.f;
            a0l = a0h = a1l = a1h = a2l = a2h = a3l = a3h = pack2(z, z);
        }
        const ulonglong2* Wp = reinterpret_cast<const ulonglong2*>(Ws);
        #pragma unroll 4
        for (int k = 0; k < F; k += 4) {
            float xv0[4], xv1[4], xv2[4], xv3[4];
            *(float4*)xv0 = *(const float4*)(xr0 + k);
            *(float4*)xv1 = *(const float4*)(xr1 + k);
            *(float4*)xv2 = *(const float4*)(xr2 + k);
            *(float4*)xv3 = *(const float4*)(xr3 + k);
            #pragma unroll
            for (int j = 0; j < 4; j++) {
                ulonglong2 w = Wp[(k + j) * 32 + tx];
                u64 p0 = pack2(xv0[j], xv0[j]);
                u64 p1 = pack2(xv1[j], xv1[j]);
                u64 p2 = pack2(xv2[j], xv2[j]);
                u64 p3 = pack2(xv3[j], xv3[j]);
                a0l = fma2(p0, w.x, a0l); a0h = fma2(p0, w.y, a0h);
                a1l = fma2(p1, w.x, a1l); a1h = fma2(p1, w.y, a1h);
                a2l = fma2(p2, w.x, a2l); a2h = fma2(p2, w.y, a2h);
                a3l = fma2(p3, w.x, a3l); a3h = fma2(p3, w.y, a3h);
            }
        }
        float4 o0, o1, o2, o3;
        unpack2(a0l, o0.x, o0.y); unpack2(a0h, o0.z, o0.w);
        unpack2(a1l, o1.x, o1.y); unpack2(a1h, o1.z, o1.w);
        unpack2(a2l, o2.x, o2.y); unpack2(a2h, o2.z, o2.w);
        unpack2(a3l, o3.x, o3.y); unpack2(a3h, o3.z, o3.w);
        int gr0 = row0 + ty * 4;
        if (gr0 + 0 < NN) ((float4*)g_xw)[(size_t)(gr0 + 0) * 32 + tx] = o0;
        if (gr0 + 1 < NN) ((float4*)g_xw)[(size_t)(gr0 + 1) * 32 + tx] = o1;
        if (gr0 + 2 < NN) ((float4*)g_xw)[(size_t)(gr0 + 2) * 32 + tx] = o2;
        if (gr0 + 3 < NN) ((float4*)g_xw)[(size_t)(gr0 + 3) * 32 + tx] = o3;
    }
}

// ---------------- fused gather + self-loop + relu + head ---------------------
// warp per node: acc = xw[i]*dinv^2 + bias + sum_{edges} xw[row]*coef
// out[i] = dot(relu(acc), lin_w) + lin_b
__global__ void k_gather(const float* __restrict__ conv_bias,
                         const float* __restrict__ lin_w,
                         const float* __restrict__ lin_b,
                         float* __restrict__ out) {
    int gw = (blockIdx.x * blockDim.x + threadIdx.x) >> 5;
    int lane = threadIdx.x & 31;
    if (gw >= NN) return;
    int s = g_rowstart[gw];
    int e = g_rowstart[gw + 1];
    float di = g_dinv[gw];
    float s2 = di * di;
    float4 acc = ((const float4*)(g_xw + (size_t)gw * F))[lane];
    float4 b = ((const float4*)conv_bias)[lane];
    acc.x = acc.x * s2 + b.x; acc.y = acc.y * s2 + b.y;
    acc.z = acc.z * s2 + b.z; acc.w = acc.w * s2 + b.w;
    for (int base = s; base < e; base += 32) {
        int idx = base + lane;
        int r = 0; float dr = 0.f;
        if (idx < e) {
            r = __ldg(g_srcrow + idx);
            dr = __ldg(g_dinv + r);
        }
        int n = min(32, e - base);
        for (int j = 0; j < n; j++) {
            int row = __shfl_sync(0xFFFFFFFFu, r, j);
            float c = __shfl_sync(0xFFFFFFFFu, dr, j) * di;
            float4 v = ((const float4*)(g_xw + (size_t)row * F))[lane];
            acc.x += v.x * c; acc.y += v.y * c;
            acc.z += v.z * c; acc.w += v.w * c;
        }
    }
    float4 lw = ((const float4*)lin_w)[lane];
    float pr = fmaxf(acc.x, 0.f) * lw.x + fmaxf(acc.y, 0.f) * lw.y
             + fmaxf(acc.z, 0.f) * lw.z + fmaxf(acc.w, 0.f) * lw.w;
    #pragma unroll
    for (int off = 16; off > 0; off >>= 1)
        pr += __shfl_xor_sync(0xFFFFFFFFu, pr, off);
    if (lane == 0) out[gw] = pr + lin_b[0];
}

// ---------------- launcher ---------------------------------------------------
extern "C" void kernel_launch(void* const* d_in, const int* in_sizes, int n_in,
                              void* d_out, int out_size) {
    const float* x         = (const float*)d_in[0];
    const int*   ei        = (const int*)d_in[1];
    const float* W         = (const float*)d_in[2];
    const float* p         = (const float*)d_in[3];
    const float* w_ih      = (const float*)d_in[4];
    const float* w_hh      = (const float*)d_in[5];
    const float* b_ih      = (const float*)d_in[6];
    const float* b_hh      = (const float*)d_in[7];
    const float* conv_bias = (const float*)d_in[8];
    const float* lin_w     = (const float*)d_in[9];
    const float* lin_b     = (const float*)d_in[10];
    float* out = (float*)d_out;

    cudaFuncSetAttribute(k_xw, cudaFuncAttributeMaxDynamicSharedMemorySize, 81920);

    k_prep<<<1, 128>>>(p);
    k_scores<<<(NN * 32 + 255) / 256, 256>>>(x, p);
    k_radix<<<1, 1024>>>();
    k_collect<<<(NN + 255) / 256, 256>>>();
    k_sort<<<1, 1024>>>();
    k_xtilde<<<KSEL, F>>>(x);
    k_gru<<<F, F>>>(W, w_ih, w_hh, b_ih, b_hh);
    k_degcnt<<<(NE + 255) / 256, 256>>>(ei);
    k_scan1<<<SCAN_BLK, 1024>>>();
    k_scan2<<<1, 32>>>();
    k_scan3<<<(NN + 255) / 256, 256>>>();
    k_fill<<<(NE + 255) / 256, 256>>>(ei);
    k_xw<<<304, 256, 81920>>>(x);
    k_gather<<<(NN * 32 + 255) / 256, 256>>>(conv_bias, lin_w, lin_b, out);
}

// round 9
// speedup vs baseline: 1.5425x; 1.1409x over previous
#include <cuda_runtime.h>
#include <cuda_fp16.h>
#include <math.h>
#include <stdint.h>

#define NN 100000
#define NE 1600000
#define F 128
#define KSEL 128
#define CAND_CAP 2048
#define SCAN_BLK 25          // ceil(100000 / 4096)

typedef unsigned long long u64;

// ---------------- scratch (device globals; no allocations allowed) ----------
static __device__ unsigned int g_keys[NN];
static __device__ int          g_deg[NN];
static __device__ float        g_dinv[NN];
static __device__ int          g_rowstart[NN + 1];
static __device__ int          g_cursor[NN];
static __device__ int          g_srcrow[NE];
static __device__ int          g_bsum[32];
static __device__ int          g_boff[32];
static __device__ unsigned int g_xwh[(size_t)NN * (F / 2)];   // xw in fp16 (2 per uint)
static __device__ float        g_xt[KSEL * F];
static __device__ float        g_Wnew[F * F];
static __device__ float        g_inv_norm;
static __device__ unsigned int g_thresh;
static __device__ int          g_ncand;
static __device__ unsigned long long g_cand[CAND_CAP];
static __device__ int          g_top_idx[KSEL];
static __device__ float        g_top_gate[KSEL];

// ---------------- packed helpers ---------------------------------------------
__device__ __forceinline__ u64 pack2(float lo, float hi) {
    u64 r; asm("mov.b64 %0, {%1, %2};" : "=l"(r) : "f"(lo), "f"(hi)); return r;
}
__device__ __forceinline__ void unpack2(u64 v, float& lo, float& hi) {
    asm("mov.b64 {%0, %1}, %2;" : "=f"(lo), "=f"(hi) : "l"(v));
}
__device__ __forceinline__ u64 fma2(u64 a, u64 b, u64 c) {
    u64 d; asm("fma.rn.f32x2 %0, %1, %2, %3;" : "=l"(d) : "l"(a), "l"(b), "l"(c)); return d;
}
__device__ __forceinline__ unsigned int h2_to_u32(__half2 h) {
    return *reinterpret_cast<unsigned int*>(&h);
}
__device__ __forceinline__ float2 u32_to_f2(unsigned int u) {
    __half2 h = *reinterpret_cast<__half2*>(&u);
    return __half22float2(h);
}

// ---------------- prep: ||p||^-1 and counter reset ---------------------------
__global__ void k_prep(const float* __restrict__ p) {
    __shared__ float red[128];
    int t = threadIdx.x;
    float v = p[t];
    red[t] = v * v;
    __syncthreads();
    for (int s = 64; s > 0; s >>= 1) {
        if (t < s) red[t] += red[t + s];
        __syncthreads();
    }
    if (t == 0) {
        g_inv_norm = 1.0f / sqrtf(red[0]);
        g_ncand = 0;
    }
}

// ---------------- scores: warp-per-node dot(x[i], p); zero deg ---------------
__global__ void k_scores(const float* __restrict__ x, const float* __restrict__ p) {
    int gw = (blockIdx.x * blockDim.x + threadIdx.x) >> 5;
    int lane = threadIdx.x & 31;
    if (gw >= NN) return;
    float4 xv = ((const float4*)(x + (size_t)gw * F))[lane];
    float4 pv = ((const float4*)p)[lane];
    float s = xv.x * pv.x + xv.y * pv.y + xv.z * pv.z + xv.w * pv.w;
    #pragma unroll
    for (int off = 16; off > 0; off >>= 1)
        s += __shfl_xor_sync(0xFFFFFFFFu, s, off);
    if (lane == 0) {
        // selection order invariant to positive scale 1/||p||; applied at gate.
        unsigned int b = __float_as_uint(s);
        unsigned int u = (b & 0x80000000u) ? ~b : (b | 0x80000000u);
        g_keys[gw] = u;
        g_deg[gw] = 0;
    }
}

// ---------------- exact 128th-largest key via 4x8-bit radix select -----------
__global__ void k_radix() {
    __shared__ unsigned int hist[256];
    __shared__ unsigned int s_prefix;
    __shared__ unsigned int s_krem;
    if (threadIdx.x == 0) { s_prefix = 0u; s_krem = KSEL; }
    for (int shift = 24; shift >= 0; shift -= 8) {
        if (threadIdx.x < 256) hist[threadIdx.x] = 0u;
        __syncthreads();
        unsigned int prefix = s_prefix;
        unsigned int maskhi = (shift == 24) ? 0u : (0xFFFFFFFFu << (shift + 8));
        for (int i = threadIdx.x; i < NN; i += blockDim.x) {
            unsigned int k = g_keys[i];
            if ((k & maskhi) == prefix)
                atomicAdd(&hist[(k >> shift) & 0xFFu], 1u);
        }
        __syncthreads();
        if (threadIdx.x == 0) {
            unsigned int cum = 0, krem = s_krem;
            int b = 255;
            for (; b >= 0; b--) {
                if (cum + hist[b] >= krem) break;
                cum += hist[b];
            }
            if (b < 0) b = 0;
            s_krem = krem - cum;
            s_prefix = prefix | ((unsigned int)b << shift);
        }
        __syncthreads();
    }
    if (threadIdx.x == 0) g_thresh = s_prefix;
}

// ---------------- collect candidates with key >= threshold -------------------
__global__ void k_collect() {
    int i = blockIdx.x * blockDim.x + threadIdx.x;
    if (i >= NN) return;
    unsigned int u = g_keys[i];
    if (u >= g_thresh) {
        int pos = atomicAdd(&g_ncand, 1);
        if (pos < CAND_CAP)
            g_cand[pos] = ((unsigned long long)u << 32)
                        | (unsigned long long)(0xFFFFFFFFu - (unsigned int)i);
    }
}

// ---------------- sort candidates desc (key, then idx asc), emit top-128 -----
__global__ void k_sort() {
    __shared__ unsigned long long s[CAND_CAP];
    __shared__ int sm_m;
    int tid = threadIdx.x;
    int n = g_ncand; if (n > CAND_CAP) n = CAND_CAP;
    if (tid == 0) {
        int m = 256;
        while (m < n) m <<= 1;
        sm_m = m;
    }
    __syncthreads();
    int m = sm_m;
    for (int i = tid; i < m; i += blockDim.x)
        s[i] = (i < n) ? g_cand[i] : 0ull;
    __syncthreads();
    for (int k = 2; k <= m; k <<= 1) {
        for (int j = k >> 1; j > 0; j >>= 1) {
            for (int i = tid; i < m; i += blockDim.x) {
                int ixj = i ^ j;
                if (ixj > i) {
                    bool desc = ((i & k) == 0);
                    unsigned long long a = s[i], b = s[ixj];
                    bool swap = desc ? (a < b) : (a > b);
                    if (swap) { s[i] = b; s[ixj] = a; }
                }
            }
            __syncthreads();
        }
    }
    if (tid < KSEL) {
        unsigned long long v = s[tid];
        unsigned int u = (unsigned int)(v >> 32);
        int idx = (int)(0xFFFFFFFFu - (unsigned int)(v & 0xFFFFFFFFu));
        unsigned int b = (u & 0x80000000u) ? (u & 0x7FFFFFFFu) : ~u;
        float sc = __uint_as_float(b) * g_inv_norm;   // apply 1/||p|| here
        g_top_idx[tid] = idx;
        g_top_gate[tid] = tanhf(sc);
    }
}

// ---------------- x_tilde[j] = x[top_idx[j]] * tanh(top_val[j]) --------------
__global__ void k_xtilde(const float* __restrict__ x) {
    int j = blockIdx.x, c = threadIdx.x;
    int idx = g_top_idx[j];
    float gate = g_top_gate[j];
    g_xt[j * F + c] = x[(size_t)idx * F + c] * gate;
}

// ---------------- GRU step: W_new -------------------------------------------
__global__ void k_gru(const float* __restrict__ W,
                      const float* __restrict__ w_ih, const float* __restrict__ w_hh,
                      const float* __restrict__ b_ih, const float* __restrict__ b_hh) {
    int r = blockIdx.x, c = threadIdx.x;
    __shared__ float xt[F];
    __shared__ float wr[F];
    xt[c] = g_xt[r * F + c];
    wr[c] = W[r * F + c];
    __syncthreads();
    const float* wi0 = w_ih + (size_t)c * F;
    const float* wi1 = w_ih + (size_t)(F + c) * F;
    const float* wi2 = w_ih + (size_t)(2 * F + c) * F;
    const float* wh0 = w_hh + (size_t)c * F;
    const float* wh1 = w_hh + (size_t)(F + c) * F;
    const float* wh2 = w_hh + (size_t)(2 * F + c) * F;
    float gi0 = 0.f, gi1 = 0.f, gi2 = 0.f, gh0 = 0.f, gh1 = 0.f, gh2 = 0.f;
    #pragma unroll 8
    for (int k = 0; k < F; k++) {
        float xk = xt[k], wk = wr[k];
        gi0 += xk * __ldg(wi0 + k);
        gi1 += xk * __ldg(wi1 + k);
        gi2 += xk * __ldg(wi2 + k);
        gh0 += wk * __ldg(wh0 + k);
        gh1 += wk * __ldg(wh1 + k);
        gh2 += wk * __ldg(wh2 + k);
    }
    gi0 += b_ih[c];         gh0 += b_hh[c];
    gi1 += b_ih[F + c];     gh1 += b_hh[F + c];
    gi2 += b_ih[2 * F + c]; gh2 += b_hh[2 * F + c];
    float rg = 1.f / (1.f + expf(-(gi0 + gh0)));
    float z  = 1.f / (1.f + expf(-(gi1 + gh1)));
    float nn = tanhf(gi2 + rg * gh2);
    g_Wnew[r * F + c] = (1.f - z) * nn + z * wr[c];
}

// ---------------- degree count ----------------------------------------------
__global__ void k_degcnt(const int* __restrict__ ei) {
    int e = blockIdx.x * blockDim.x + threadIdx.x;
    if (e >= NE) return;
    atomicAdd(&g_deg[ei[NE + e]], 1);
}

// ---------------- 3-kernel exclusive prefix scan of degrees ------------------
__global__ void k_scan1() {
    __shared__ int ssum[1024];
    int bid = blockIdx.x, t = threadIdx.x;
    int base = bid * 4096 + t * 4;
    int v[4]; int s = 0;
    #pragma unroll
    for (int j = 0; j < 4; j++) {
        int idx = base + j;
        v[j] = (idx < NN) ? g_deg[idx] : 0;
        s += v[j];
    }
    ssum[t] = s;
    __syncthreads();
    for (int off = 1; off < 1024; off <<= 1) {
        int xv = (t >= off) ? ssum[t - off] : 0;
        __syncthreads();
        ssum[t] += xv;
        __syncthreads();
    }
    int run = ssum[t] - s;   // exclusive within block
    if (t == 1023) g_bsum[bid] = ssum[1023];
    #pragma unroll
    for (int j = 0; j < 4; j++) {
        int idx = base + j;
        if (idx < NN) g_rowstart[idx] = run;
        run += v[j];
    }
}

__global__ void k_scan2() {
    int t = threadIdx.x;
    int v = (t < SCAN_BLK) ? g_bsum[t] : 0;
    int orig = v;
    #pragma unroll
    for (int off = 1; off < 32; off <<= 1) {
        int u = __shfl_up_sync(0xFFFFFFFFu, v, off);
        if (t >= off) v += u;
    }
    g_boff[t] = v - orig;    // exclusive
}

__global__ void k_scan3() {
    int i = blockIdx.x * blockDim.x + threadIdx.x;
    if (i >= NN) return;
    int r = g_rowstart[i] + g_boff[i >> 12];
    g_rowstart[i] = r;
    g_cursor[i] = r;
    g_dinv[i] = rsqrtf((float)g_deg[i] + 1.0f);
    if (i == 0) g_rowstart[NN] = NE;
}

// ---------------- fill CSR: srcrow bucketed by col ---------------------------
__global__ void k_fill(const int* __restrict__ ei) {
    int e = blockIdx.x * blockDim.x + threadIdx.x;
    if (e >= NE) return;
    int row = __ldg(ei + e);
    int col = __ldg(ei + NE + e);
    int pos = atomicAdd(&g_cursor[col], 1);
    g_srcrow[pos] = row;
}

// ---------------- xw = x @ W_new (packed f32x2 FMA, fp16 output) -------------
__global__ void __launch_bounds__(256, 2) k_xw(const float* __restrict__ x) {
    extern __shared__ float smem[];
    float4* Ws = reinterpret_cast<float4*>(smem);     // [128 k][32 colgrp] float4 = 64 KB
    float*  xs = smem + F * F;                        // [32 rows][128] floats = 16 KB
    int tx = threadIdx.x & 31;
    int ty = threadIdx.x >> 5;
    for (int i = threadIdx.x; i < F * 32; i += 256)
        Ws[i] = ((const float4*)g_Wnew)[i];
    int ntiles = (NN + 31) / 32;
    for (int t = blockIdx.x; t < ntiles; t += gridDim.x) {
        int row0 = t * 32;
        __syncthreads();
        for (int i = threadIdx.x; i < 32 * 32; i += 256) {
            int r = i >> 5, q = i & 31;
            int gr = row0 + r;
            float4 v = (gr < NN) ? ((const float4*)x)[(size_t)gr * 32 + q]
                                 : make_float4(0.f, 0.f, 0.f, 0.f);
            ((float4*)xs)[i] = v;
        }
        __syncthreads();
        const float* xr0 = xs + (ty * 4 + 0) * F;
        const float* xr1 = xs + (ty * 4 + 1) * F;
        const float* xr2 = xs + (ty * 4 + 2) * F;
        const float* xr3 = xs + (ty * 4 + 3) * F;
        u64 zz = pack2(0.f, 0.f);
        u64 a0l = zz, a0h = zz, a1l = zz, a1h = zz;
        u64 a2l = zz, a2h = zz, a3l = zz, a3h = zz;
        const ulonglong2* Wp = reinterpret_cast<const ulonglong2*>(Ws);
        #pragma unroll 4
        for (int k = 0; k < F; k += 4) {
            float xv0[4], xv1[4], xv2[4], xv3[4];
            *(float4*)xv0 = *(const float4*)(xr0 + k);
            *(float4*)xv1 = *(const float4*)(xr1 + k);
            *(float4*)xv2 = *(const float4*)(xr2 + k);
            *(float4*)xv3 = *(const float4*)(xr3 + k);
            #pragma unroll
            for (int j = 0; j < 4; j++) {
                ulonglong2 w = Wp[(k + j) * 32 + tx];
                u64 p0 = pack2(xv0[j], xv0[j]);
                u64 p1 = pack2(xv1[j], xv1[j]);
                u64 p2 = pack2(xv2[j], xv2[j]);
                u64 p3 = pack2(xv3[j], xv3[j]);
                a0l = fma2(p0, w.x, a0l); a0h = fma2(p0, w.y, a0h);
                a1l = fma2(p1, w.x, a1l); a1h = fma2(p1, w.y, a1h);
                a2l = fma2(p2, w.x, a2l); a2h = fma2(p2, w.y, a2h);
                a3l = fma2(p3, w.x, a3l); a3h = fma2(p3, w.y, a3h);
            }
        }
        float4 o0, o1, o2, o3;
        unpack2(a0l, o0.x, o0.y); unpack2(a0h, o0.z, o0.w);
        unpack2(a1l, o1.x, o1.y); unpack2(a1h, o1.z, o1.w);
        unpack2(a2l, o2.x, o2.y); unpack2(a2h, o2.z, o2.w);
        unpack2(a3l, o3.x, o3.y); unpack2(a3h, o3.z, o3.w);
        int gr0 = row0 + ty * 4;
        if (gr0 + 0 < NN) {
            uint2 u; u.x = h2_to_u32(__floats2half2_rn(o0.x, o0.y));
                     u.y = h2_to_u32(__floats2half2_rn(o0.z, o0.w));
            ((uint2*)(g_xwh + (size_t)(gr0 + 0) * (F / 2)))[tx] = u;
        }
        if (gr0 + 1 < NN) {
            uint2 u; u.x = h2_to_u32(__floats2half2_rn(o1.x, o1.y));
                     u.y = h2_to_u32(__floats2half2_rn(o1.z, o1.w));
            ((uint2*)(g_xwh + (size_t)(gr0 + 1) * (F / 2)))[tx] = u;
        }
        if (gr0 + 2 < NN) {
            uint2 u; u.x = h2_to_u32(__floats2half2_rn(o2.x, o2.y));
                     u.y = h2_to_u32(__floats2half2_rn(o2.z, o2.w));
            ((uint2*)(g_xwh + (size_t)(gr0 + 2) * (F / 2)))[tx] = u;
        }
        if (gr0 + 3 < NN) {
            uint2 u; u.x = h2_to_u32(__floats2half2_rn(o3.x, o3.y));
                     u.y = h2_to_u32(__floats2half2_rn(o3.z, o3.w));
            ((uint2*)(g_xwh + (size_t)(gr0 + 3) * (F / 2)))[tx] = u;
        }
    }
}

// ---------------- fused gather + self-loop + relu + head ---------------------
// warp per node, fp16 xw rows, fp32 accumulate:
// acc = xw[i]*dinv^2 + bias + sum_{edges} xw[row]*coef
// out[i] = dot(relu(acc), lin_w) + lin_b
__global__ void k_gather(const float* __restrict__ conv_bias,
                         const float* __restrict__ lin_w,
                         const float* __restrict__ lin_b,
                         float* __restrict__ out) {
    int gw = (blockIdx.x * blockDim.x + threadIdx.x) >> 5;
    int lane = threadIdx.x & 31;
    if (gw >= NN) return;
    int s = g_rowstart[gw];
    int e = g_rowstart[gw + 1];
    float di = g_dinv[gw];
    float s2 = di * di;
    float4 acc;
    {
        uint2 raw = ((const uint2*)(g_xwh + (size_t)gw * (F / 2)))[lane];
        float2 f0 = u32_to_f2(raw.x);
        float2 f1 = u32_to_f2(raw.y);
        float4 b = ((const float4*)conv_bias)[lane];
        acc.x = f0.x * s2 + b.x; acc.y = f0.y * s2 + b.y;
        acc.z = f1.x * s2 + b.z; acc.w = f1.y * s2 + b.w;
    }
    for (int base = s; base < e; base += 32) {
        int idx = base + lane;
        int r = 0; float dr = 0.f;
        if (idx < e) {
            r = __ldg(g_srcrow + idx);
            dr = __ldg(g_dinv + r);
        }
        int n = min(32, e - base);
        for (int j = 0; j < n; j++) {
            int row = __shfl_sync(0xFFFFFFFFu, r, j);
            float c = __shfl_sync(0xFFFFFFFFu, dr, j) * di;
            uint2 raw = __ldg((const uint2*)(g_xwh + (size_t)row * (F / 2)) + lane);
            float2 f0 = u32_to_f2(raw.x);
            float2 f1 = u32_to_f2(raw.y);
            acc.x += f0.x * c; acc.y += f0.y * c;
            acc.z += f1.x * c; acc.w += f1.y * c;
        }
    }
    float4 lw = ((const float4*)lin_w)[lane];
    float pr = fmaxf(acc.x, 0.f) * lw.x + fmaxf(acc.y, 0.f) * lw.y
             + fmaxf(acc.z, 0.f) * lw.z + fmaxf(acc.w, 0.f) * lw.w;
    #pragma unroll
    for (int off = 16; off > 0; off >>= 1)
        pr += __shfl_xor_sync(0xFFFFFFFFu, pr, off);
    if (lane == 0) out[gw] = pr + lin_b[0];
}

// ---------------- launcher ---------------------------------------------------
extern "C" void kernel_launch(void* const* d_in, const int* in_sizes, int n_in,
                              void* d_out, int out_size) {
    const float* x         = (const float*)d_in[0];
    const int*   ei        = (const int*)d_in[1];
    const float* W         = (const float*)d_in[2];
    const float* p         = (const float*)d_in[3];
    const float* w_ih      = (const float*)d_in[4];
    const float* w_hh      = (const float*)d_in[5];
    const float* b_ih      = (const float*)d_in[6];
    const float* b_hh      = (const float*)d_in[7];
    const float* conv_bias = (const float*)d_in[8];
    const float* lin_w     = (const float*)d_in[9];
    const float* lin_b     = (const float*)d_in[10];
    float* out = (float*)d_out;

    cudaFuncSetAttribute(k_xw, cudaFuncAttributeMaxDynamicSharedMemorySize, 81920);

    k_prep<<<1, 128>>>(p);
    k_scores<<<(NN * 32 + 255) / 256, 256>>>(x, p);
    k_radix<<<1, 1024>>>();
    k_collect<<<(NN + 255) / 256, 256>>>();
    k_sort<<<1, 256>>>();
    k_xtilde<<<KSEL, F>>>(x);
    k_gru<<<F, F>>>(W, w_ih, w_hh, b_ih, b_hh);
    k_degcnt<<<(NE + 255) / 256, 256>>>(ei);
    k_scan1<<<SCAN_BLK, 1024>>>();
    k_scan2<<<1, 32>>>();
    k_scan3<<<(NN + 255) / 256, 256>>>();
    k_fill<<<(NE + 255) / 256, 256>>>(ei);
    k_xw<<<304, 256, 81920>>>(x);
    k_gather<<<(NN * 32 + 255) / 256, 256>>>(conv_bias, lin_w, lin_b, out);
}